// round 2
// baseline (speedup 1.0000x reference)
#include <cuda_runtime.h>

// Problem constants (fixed shapes)
#define NB 4096
#define NS 200
#define ND 64

// Dynamic smem layout (bytes):
//   Mp   @ 0      : 64*32 float2 = 16384   (Mp[k*32+i] = (M[k][i], M[k][i+32]))
//   W2p  @ 16384  : 64*16 float2 = 8192    (W2p[k*16+i] = (W2[k][i], W2[k][i+16]))
//   cp   @ 24576  : 32 float2    = 256     (cp[i] = (c[i], c[i+32]))
//   b2p  @ 24832  : 16 float2    = 128     (b2p[i] = (b2[i], b2[i+16]))
//   w3s  @ 24960  : 32 float     = 128
//   bnsc @ 25088  : 128 float    = 512
//   bnsh @ 25600  : 128 float    = 512
//   qs   @ 26112  : 64 float     = 256
//   lg   @ 26368  : 200 float    = 800
//   we   @ 27168  : 200 float    = 800
//   red  @ 27968  : 4 float      = 16
//   XsT  @ 27984  : 64*201 float = 51456   (XsT[d*201 + s] = Xu[b][s][d])
//   total 79440 -> request 79456
#define SMEM_BYTES 79456

__device__ __forceinline__ unsigned long long pack2(float a, float b) {
    unsigned long long r;
    asm("mov.b64 %0, {%1, %2};" : "=l"(r)
        : "r"(__float_as_uint(a)), "r"(__float_as_uint(b)));
    return r;
}
__device__ __forceinline__ void ffma2(unsigned long long& d,
                                      unsigned long long a,
                                      unsigned long long b) {
    asm("fma.rn.f32x2 %0, %1, %2, %0;" : "+l"(d) : "l"(a), "l"(b));
}
__device__ __forceinline__ float lo32(unsigned long long v) {
    return __uint_as_float((unsigned)v);
}
__device__ __forceinline__ float hi32(unsigned long long v) {
    return __uint_as_float((unsigned)(v >> 32));
}

extern __shared__ unsigned char smem_raw[];

__global__ void __launch_bounds__(256, 2) din_user_rep_kernel(
    const float* __restrict__ em,   const float* __restrict__ eu,
    const float* __restrict__ Xu,   const float* __restrict__ W1,
    const float* __restrict__ b1,   const float* __restrict__ W2,
    const float* __restrict__ b2,   const float* __restrict__ W3,
    const float* __restrict__ b3,   const float* __restrict__ gamma,
    const float* __restrict__ beta, const float* __restrict__ mmean,
    const float* __restrict__ mvar, float* __restrict__ out)
{
    const int t = threadIdx.x;
    const int b = blockIdx.x;

    float2* Mp   = (float2*)(smem_raw + 0);
    float2* W2p  = (float2*)(smem_raw + 16384);
    float2* cp   = (float2*)(smem_raw + 24576);
    float2* b2p  = (float2*)(smem_raw + 24832);
    float*  w3s  = (float*) (smem_raw + 24960);
    float*  bnsc = (float*) (smem_raw + 25088);
    float*  bnsh = (float*) (smem_raw + 25600);
    float*  qs   = (float*) (smem_raw + 26112);
    float*  lg   = (float*) (smem_raw + 26368);
    float*  we   = (float*) (smem_raw + 27168);
    float*  red  = (float*) (smem_raw + 27968);
    float*  XsT  = (float*) (smem_raw + 27984);

    // ---- Phase 0: query vector + BN affine fold ----
    if (t < 64) qs[t] = em[(size_t)b * 64 + t];
    if (t < 128) {
        float sc = gamma[t] * rsqrtf(mvar[t] + 1e-3f);
        bnsc[t] = sc;
        bnsh[t] = beta[t] - mmean[t] * sc;
    }
    if (t < 32) w3s[t] = W3[t];
    __syncthreads();

    // ---- Phase 1: stage Xu^T, build folded M_b, c_b, W2 pairs ----
    // Xu tile, coalesced global read, transposed store (stride 201 words:
    // bank = (9*d + s) mod 32, conflict-free for both access patterns).
    const float* Xb = Xu + (size_t)b * (NS * ND);
    for (int idx = t; idx < NS * ND; idx += 256) {
        int s = idx >> 6, d = idx & 63;
        XsT[d * 201 + s] = Xb[idx];
    }
    // M_b[k][j] = W1b[k][j] - W1c[k][j] + q_k * W1d[k][j], pair-interleaved.
    for (int e = t; e < 2048; e += 256) {
        int k = e >> 5, i = e & 31;
        float qk = qs[k];
        const float* wb = W1 + (64 + k) * 64;
        const float* wc = W1 + (128 + k) * 64;
        const float* wd = W1 + (192 + k) * 64;
        float lo = wb[i]      - wc[i]      + qk * wd[i];
        float hi = wb[i + 32] - wc[i + 32] + qk * wd[i + 32];
        Mp[e] = make_float2(lo, hi);
    }
    // c_b = b1 + q @ (W1a + W1c), pair-interleaved.
    if (t < 32) {
        float c0 = b1[t], c1 = b1[t + 32];
        for (int k = 0; k < 64; k++) {
            float qk = qs[k];
            c0 += qk * (W1[k * 64 + t]      + W1[(128 + k) * 64 + t]);
            c1 += qk * (W1[k * 64 + t + 32] + W1[(128 + k) * 64 + t + 32]);
        }
        cp[t] = make_float2(c0, c1);
    }
    // W2 pair-interleaved (j, j+16).
    for (int e = t; e < 1024; e += 256) {
        int k = e >> 4, i = e & 15;
        W2p[e] = make_float2(W2[k * 32 + i], W2[k * 32 + i + 16]);
    }
    if (t < 16) b2p[t] = make_float2(b2[t], b2[t + 16]);
    __syncthreads();

    // ---- Phase 2: per-row MLP, one lane per sequence position ----
    float logit = 0.f;
    if (t < NS) {
        const int s = t;
        // Layer 1: h1 = relu(Xu_row @ M_b + c_b), 64 outputs as 32 f32x2 pairs.
        unsigned long long acc[32];
        const unsigned long long* cpu = (const unsigned long long*)cp;
        #pragma unroll
        for (int i = 0; i < 32; i++) acc[i] = cpu[i];

        const ulonglong2* Mp2 = (const ulonglong2*)Mp;
        for (int k = 0; k < 64; k++) {
            float x = XsT[k * 201 + s];
            unsigned long long xx = pack2(x, x);
            #pragma unroll
            for (int p = 0; p < 16; p++) {
                ulonglong2 m = Mp2[k * 16 + p];   // broadcast, 16B
                ffma2(acc[2 * p],     xx, m.x);
                ffma2(acc[2 * p + 1], xx, m.y);
            }
        }

        // Layer 2: h2 = relu(h1 @ W2 + b2), 32 outputs as 16 pairs.
        // Relu of h1 applied lazily while unpacking pairs (k, k+32).
        unsigned long long accB[16];
        const unsigned long long* b2u = (const unsigned long long*)b2p;
        #pragma unroll
        for (int i = 0; i < 16; i++) accB[i] = b2u[i];

        const ulonglong2* W2p2 = (const ulonglong2*)W2p;
        for (int kk = 0; kk < 32; kk++) {
            float hl = fmaxf(lo32(acc[kk]), 0.f);   // h1[kk]
            float hh = fmaxf(hi32(acc[kk]), 0.f);   // h1[kk+32]
            unsigned long long xl = pack2(hl, hl);
            unsigned long long xh = pack2(hh, hh);
            #pragma unroll
            for (int p = 0; p < 8; p++) {
                ulonglong2 wl = W2p2[kk * 8 + p];
                ffma2(accB[2 * p],     xl, wl.x);
                ffma2(accB[2 * p + 1], xl, wl.y);
            }
            #pragma unroll
            for (int p = 0; p < 8; p++) {
                ulonglong2 wh = W2p2[(kk + 32) * 8 + p];
                ffma2(accB[2 * p],     xh, wh.x);
                ffma2(accB[2 * p + 1], xh, wh.y);
            }
        }

        // Layer 3: logit = relu(h2) @ W3 + b3 (relu lazy again).
        float l = b3[0];
        #pragma unroll
        for (int i = 0; i < 16; i++) {
            l += fmaxf(lo32(accB[i]), 0.f) * w3s[i];
            l += fmaxf(hi32(accB[i]), 0.f) * w3s[i + 16];
        }
        logit = l;
        lg[s] = l;
    }
    __syncthreads();

    // ---- Softmax reduction (warp 0) ----
    if (t < 32) {
        float m = -3.0e38f;
        for (int r = t; r < NS; r += 32) m = fmaxf(m, lg[r]);
        #pragma unroll
        for (int o = 16; o; o >>= 1) m = fmaxf(m, __shfl_xor_sync(0xffffffffu, m, o));
        float ssum = 0.f;
        for (int r = t; r < NS; r += 32) ssum += __expf(lg[r] - m);
        #pragma unroll
        for (int o = 16; o; o >>= 1) ssum += __shfl_xor_sync(0xffffffffu, ssum, o);
        if (t == 0) { red[0] = m; red[1] = 1.f / ssum; }
    }
    __syncthreads();
    if (t < NS) we[t] = __expf(logit - red[0]) * red[1];
    __syncthreads();

    // ---- Pool + BN + output assembly: out row = [bn(pooled), bn(em), eu] ----
    float* ob = out + (size_t)b * 192;
    if (t < 64) {
        float p = 0.f;
        const float* xr = XsT + t * 201;
        #pragma unroll 4
        for (int s = 0; s < NS; s++) p += we[s] * xr[s];
        ob[t] = p * bnsc[t] + bnsh[t];
    } else if (t < 128) {
        ob[t] = qs[t - 64] * bnsc[t] + bnsh[t];
    } else if (t < 192) {
        ob[t] = eu[(size_t)b * 64 + (t - 128)];
    }
}

extern "C" void kernel_launch(void* const* d_in, const int* in_sizes, int n_in,
                              void* d_out, int out_size) {
    (void)in_sizes; (void)n_in; (void)out_size;
    cudaFuncSetAttribute(din_user_rep_kernel,
                         cudaFuncAttributeMaxDynamicSharedMemorySize, SMEM_BYTES);
    din_user_rep_kernel<<<NB, 256, SMEM_BYTES>>>(
        (const float*)d_in[0],  // em
        (const float*)d_in[1],  // eu
        (const float*)d_in[2],  // Xu
        (const float*)d_in[3],  // W1
        (const float*)d_in[4],  // b1
        (const float*)d_in[5],  // W2
        (const float*)d_in[6],  // b2
        (const float*)d_in[7],  // W3
        (const float*)d_in[8],  // b3
        (const float*)d_in[9],  // gamma
        (const float*)d_in[10], // beta
        (const float*)d_in[11], // mov_mean
        (const float*)d_in[12], // mov_var
        (float*)d_out);
}

// round 3
// speedup vs baseline: 1.2759x; 1.2759x over previous
#include <cuda_runtime.h>

// Fixed shapes
#define NB 4096
#define NS 200
#define ND 64
#define XST 212   // XsT row stride in floats (mult of 4 -> float4-aligned rows)

// smem offsets (bytes), all 16B-aligned
#define OFF_MS    0        // 64*64 floats, chunk-permuted rows     (16384)
#define OFF_W2S   16384    // 64*32 floats + 8-float skew / 16 rows (8448)
#define OFF_CS    24832    // 64 floats  layer-1 bias c_b           (256)
#define OFF_B2S   25088    // 32 floats                              (128)
#define OFF_W3S   25216    // 32 floats                              (128)
#define OFF_BNSC  25344    // 128 floats                             (512)
#define OFF_BNSH  25856    // 128 floats                             (512)
#define OFF_QS    26368    // 64 floats                              (256)
#define OFF_LG    26624    // 200 floats                             (800)
#define OFF_WE    27424    // 200 floats (float4-aligned)            (800)
#define OFF_RED   28224    // red[0]=max red[1]=1/sum red[2]=b3      (16)
#define OFF_XST   28240    // 64*212 floats + 48 pad                 (54464)
#define SMEM_BYTES 82720

typedef unsigned long long u64;

__device__ __forceinline__ u64 pack2(float a, float b) {
    u64 r;
    asm("mov.b64 %0, {%1, %2};" : "=l"(r)
        : "r"(__float_as_uint(a)), "r"(__float_as_uint(b)));
    return r;
}
__device__ __forceinline__ void ffma2(u64& d, u64 a, u64 b) {
    asm("fma.rn.f32x2 %0, %1, %2, %0;" : "+l"(d) : "l"(a), "l"(b));
}
__device__ __forceinline__ void add2(u64& d, u64 a) {
    asm("add.rn.f32x2 %0, %0, %1;" : "+l"(d) : "l"(a));
}
__device__ __forceinline__ float lo32(u64 v) { return __uint_as_float((unsigned)v); }
__device__ __forceinline__ float hi32(u64 v) { return __uint_as_float((unsigned)(v >> 32)); }
__device__ __forceinline__ u64 shflx64(u64 v, int m) {
    double d = __longlong_as_double((long long)v);
    d = __shfl_xor_sync(0xffffffffu, d, m);
    return (u64)__double_as_longlong(d);
}

extern __shared__ unsigned char smem_raw[];

__global__ void __launch_bounds__(256, 2) din_user_rep_kernel(
    const float* __restrict__ em,   const float* __restrict__ eu,
    const float* __restrict__ Xu,   const float* __restrict__ W1,
    const float* __restrict__ b1,   const float* __restrict__ W2,
    const float* __restrict__ b2,   const float* __restrict__ W3,
    const float* __restrict__ b3,   const float* __restrict__ gamma,
    const float* __restrict__ beta, const float* __restrict__ mmean,
    const float* __restrict__ mvar, float* __restrict__ out)
{
    const int t = threadIdx.x;
    const int b = blockIdx.x;

    float* Ms   = (float*)(smem_raw + OFF_MS);
    float* W2s  = (float*)(smem_raw + OFF_W2S);
    float* cs   = (float*)(smem_raw + OFF_CS);
    float* b2s  = (float*)(smem_raw + OFF_B2S);
    float* w3s  = (float*)(smem_raw + OFF_W3S);
    float* bnsc = (float*)(smem_raw + OFF_BNSC);
    float* bnsh = (float*)(smem_raw + OFF_BNSH);
    float* qs   = (float*)(smem_raw + OFF_QS);
    float* lg   = (float*)(smem_raw + OFF_LG);
    float* we   = (float*)(smem_raw + OFF_WE);
    float* red  = (float*)(smem_raw + OFF_RED);
    float* XsT  = (float*)(smem_raw + OFF_XST);

    // ---- Phase 0: per-batch vectors + parameter staging (no cross-deps) ----
    if (t < 64)  qs[t] = em[(size_t)b * 64 + t];
    if (t < 128) {
        float sc = gamma[t] * rsqrtf(mvar[t] + 1e-3f);
        bnsc[t] = sc;
        bnsh[t] = beta[t] - mmean[t] * sc;
    }
    if (t < 32) { w3s[t] = W3[t]; b2s[t] = b2[t]; }
    if (t == 0) red[2] = b3[0];

    // W2 -> smem with +8-float skew per 16-row block (bank decollision for ct lanes)
    for (int e = t; e < 2048; e += 256) {
        int k = e >> 5, j = e & 31;
        W2s[k * 32 + (k >> 4) * 8 + j] = W2[e];
    }

    // Xu transpose staging: thread handles (d, s-chunk); global reads coalesced
    // per sub-row (lanes span consecutive d), smem stores contiguous STS.128.
    const float* Xb = Xu + (size_t)b * (NS * ND);
    for (int e = t; e < 64 * 50; e += 256) {
        int d = e & 63, sc = e >> 6;
        float x0 = Xb[(4 * sc + 0) * 64 + d];
        float x1 = Xb[(4 * sc + 1) * 64 + d];
        float x2 = Xb[(4 * sc + 2) * 64 + d];
        float x3 = Xb[(4 * sc + 3) * 64 + d];
        *(float4*)(XsT + d * XST + 4 * sc) = make_float4(x0, x1, x2, x3);
    }
    __syncthreads();   // qs ready for folds

    // ---- Phase 1: folded layer-1 weights ----
    // M[k][c] = W1b[k][c] - W1c[k][c] + q_k * W1d[k][c], chunk-permuted columns:
    // 16B chunk h=c>>2 stored at slot 4*(h&3)+(h>>2) so ct lanes hit distinct banks.
    for (int e = t; e < 4096; e += 256) {
        int k = e >> 6, c = e & 63;
        float qk = qs[k];
        float v = W1[(64 + k) * 64 + c] - W1[(128 + k) * 64 + c]
                + qk * W1[(192 + k) * 64 + c];
        int h = c >> 2, l = c & 3;
        int slot = 4 * (h & 3) + (h >> 2);
        Ms[k * 64 + slot * 4 + l] = v;
    }
    // c_b = b1 + q @ (W1a + W1c)
    if (t < 64) {
        float c0 = b1[t];
        for (int k = 0; k < 64; k++)
            c0 += qs[k] * (W1[k * 64 + t] + W1[(128 + k) * 64 + t]);
        cs[t] = c0;
    }
    __syncthreads();

    // ---- Phase 2: register-tiled MLP ----
    // Thread tile: 4 rows (s0=4*rt) x 16 cols (c0=16*ct); rt=t>>2, ct=t&3.
    const int rt = t >> 2, ct = t & 3;
    const int s0 = 4 * rt;

    // Layer 1: acc[r][p] packed pairs, cols (16ct+2p, 16ct+2p+1)
    u64 acc[4][8];
    {
        const u64* cpp = (const u64*)(cs + 16 * ct);
        #pragma unroll
        for (int r = 0; r < 4; r++)
            #pragma unroll
            for (int p = 0; p < 8; p++) acc[r][p] = cpp[p];
    }
    #pragma unroll 4
    for (int k = 0; k < 64; k++) {
        float4 xv = *(const float4*)(XsT + k * XST + s0);
        u64 xx0 = pack2(xv.x, xv.x), xx1 = pack2(xv.y, xv.y);
        u64 xx2 = pack2(xv.z, xv.z), xx3 = pack2(xv.w, xv.w);
        const ulonglong2* mr = (const ulonglong2*)(Ms + k * 64);
        ulonglong2 m0 = mr[ct];       // cols 16ct+ 0.. 3
        ulonglong2 m1 = mr[4 + ct];   // cols 16ct+ 4.. 7
        ulonglong2 m2 = mr[8 + ct];   // cols 16ct+ 8..11
        ulonglong2 m3 = mr[12 + ct];  // cols 16ct+12..15
        #pragma unroll
        for (int r = 0; r < 4; r++) {
            u64 xr = (r == 0) ? xx0 : (r == 1) ? xx1 : (r == 2) ? xx2 : xx3;
            ffma2(acc[r][0], xr, m0.x); ffma2(acc[r][1], xr, m0.y);
            ffma2(acc[r][2], xr, m1.x); ffma2(acc[r][3], xr, m1.y);
            ffma2(acc[r][4], xr, m2.x); ffma2(acc[r][5], xr, m2.y);
            ffma2(acc[r][6], xr, m3.x); ffma2(acc[r][7], xr, m3.y);
        }
    }

    // Layer 2 + 3 in registers: each ct lane holds k in [16ct,16ct+16).
    // j-chunks of 8; partial h2 reduced over the 4-lane ct-group via shfl.bfly.
    u64 lacc[4] = {0, 0, 0, 0};
    #pragma unroll
    for (int jc = 0; jc < 4; jc++) {
        u64 hb[4][4];
        #pragma unroll
        for (int r = 0; r < 4; r++)
            #pragma unroll
            for (int p = 0; p < 4; p++) hb[r][p] = 0ull;

        const float* wbase = W2s + (16 * ct) * 32 + ct * 8 + jc * 8;
        #pragma unroll
        for (int kk = 0; kk < 16; kk++) {
            ulonglong2 wa = *(const ulonglong2*)(wbase + kk * 32);      // j0..j0+3
            ulonglong2 wb = *(const ulonglong2*)(wbase + kk * 32 + 4);  // j0+4..j0+7
            #pragma unroll
            for (int r = 0; r < 4; r++) {
                float hv = (kk & 1) ? hi32(acc[r][kk >> 1]) : lo32(acc[r][kk >> 1]);
                hv = fmaxf(hv, 0.f);                  // relu(h1)
                u64 hh = pack2(hv, hv);
                ffma2(hb[r][0], hh, wa.x); ffma2(hb[r][1], hh, wa.y);
                ffma2(hb[r][2], hh, wb.x); ffma2(hb[r][3], hh, wb.y);
            }
        }
        // reduce partial h2 over ct-group (lanes xor 1, xor 2)
        #pragma unroll
        for (int r = 0; r < 4; r++)
            #pragma unroll
            for (int p = 0; p < 4; p++) {
                add2(hb[r][p], shflx64(hb[r][p], 1));
                add2(hb[r][p], shflx64(hb[r][p], 2));
            }
        // + b2, relu, dot with W3
        const u64* b2p = (const u64*)(b2s + 8 * jc);
        const u64* w3p = (const u64*)(w3s + 8 * jc);
        #pragma unroll
        for (int r = 0; r < 4; r++)
            #pragma unroll
            for (int p = 0; p < 4; p++) {
                u64 hv2 = hb[r][p];
                add2(hv2, b2p[p]);
                float a0 = fmaxf(lo32(hv2), 0.f);
                float a1 = fmaxf(hi32(hv2), 0.f);
                ffma2(lacc[r], pack2(a0, a1), w3p[p]);
            }
    }
    if (ct == 0 && rt < 50) {
        float b3v = red[2];
        #pragma unroll
        for (int r = 0; r < 4; r++)
            lg[s0 + r] = lo32(lacc[r]) + hi32(lacc[r]) + b3v;
    }
    __syncthreads();

    // ---- Softmax reduction (warp 0) ----
    if (t < 32) {
        float m = -3.0e38f;
        for (int r = t; r < NS; r += 32) m = fmaxf(m, lg[r]);
        #pragma unroll
        for (int o = 16; o; o >>= 1) m = fmaxf(m, __shfl_xor_sync(0xffffffffu, m, o));
        float ssum = 0.f;
        for (int r = t; r < NS; r += 32) ssum += __expf(lg[r] - m);
        #pragma unroll
        for (int o = 16; o; o >>= 1) ssum += __shfl_xor_sync(0xffffffffu, ssum, o);
        if (t == 0) { red[0] = m; red[1] = 1.f / ssum; }
    }
    __syncthreads();
    if (t < NS) we[t] = __expf(lg[t] - red[0]) * red[1];
    __syncthreads();

    // ---- Pool + BN + output: out row = [bn(pooled), bn(em), eu] ----
    float* ob = out + (size_t)b * 192;
    if (t < 64) {
        const float4* xr = (const float4*)(XsT + t * XST);
        const float4* wv = (const float4*)we;
        float p = 0.f;
        #pragma unroll 5
        for (int sc = 0; sc < 50; sc++) {
            float4 x = xr[sc], w = wv[sc];
            p += x.x * w.x + x.y * w.y + x.z * w.z + x.w * w.w;
        }
        ob[t] = p * bnsc[t] + bnsh[t];
    } else if (t < 128) {
        ob[t] = qs[t - 64] * bnsc[t] + bnsh[t];
    } else if (t < 192) {
        ob[t] = eu[(size_t)b * 64 + (t - 128)];
    }
}

extern "C" void kernel_launch(void* const* d_in, const int* in_sizes, int n_in,
                              void* d_out, int out_size) {
    (void)in_sizes; (void)n_in; (void)out_size;
    cudaFuncSetAttribute(din_user_rep_kernel,
                         cudaFuncAttributeMaxDynamicSharedMemorySize, SMEM_BYTES);
    din_user_rep_kernel<<<NB, 256, SMEM_BYTES>>>(
        (const float*)d_in[0],  // em
        (const float*)d_in[1],  // eu
        (const float*)d_in[2],  // Xu
        (const float*)d_in[3],  // W1
        (const float*)d_in[4],  // b1
        (const float*)d_in[5],  // W2
        (const float*)d_in[6],  // b2
        (const float*)d_in[7],  // W3
        (const float*)d_in[8],  // b3
        (const float*)d_in[9],  // gamma
        (const float*)d_in[10], // beta
        (const float*)d_in[11], // mov_mean
        (const float*)d_in[12], // mov_var
        (float*)d_out);
}